// round 12
// baseline (speedup 1.0000x reference)
#include <cuda_runtime.h>
#include <cstdint>

#define BATCH 2
#define C     48
#define C3    144
#define DD    32
#define HD    64
#define WD    64
#define LL    (DD*HD*WD)   /* 131072 */
#define HW    (HD*WD)      /* 4096 */
#define HEADS 6
#define CPH   8

#define XPITCH 136                     /* smem pitch (words): bank = 8*t4+g, conflict-free */
#define SM_TC  (2 * 48 * XPITCH * 4)   /* hi+lo staged tile bytes = 52224 */

// ---- scratch ----
__device__ float g_qkv[(size_t)BATCH * C3 * LL];
__device__ float g_dw [(size_t)BATCH * C3 * LL];
__device__ float g_attn[BATCH * HEADS * CPH * CPH];
__device__ float g_weff[BATCH * C * C];

// ---- tf32 helpers ----
__device__ __forceinline__ uint32_t f2tf32(float f) {
    uint32_t r; asm("cvt.rna.tf32.f32 %0, %1;" : "=r"(r) : "f"(f)); return r;
}
__device__ __forceinline__ void mma_tf32(float& c0, float& c1, float& c2, float& c3,
                                         uint32_t a0, uint32_t a1, uint32_t a2, uint32_t a3,
                                         uint32_t b0, uint32_t b1) {
    asm("mma.sync.aligned.m16n8k8.row.col.f32.tf32.tf32.f32 "
        "{%0,%1,%2,%3}, {%4,%5,%6,%7}, {%8,%9}, {%0,%1,%2,%3};"
        : "+f"(c0), "+f"(c1), "+f"(c2), "+f"(c3)
        : "r"(a0), "r"(a1), "r"(a2), "r"(a3), "r"(b0), "r"(b1));
}

// ---------------------------------------------------------------------------
__global__ void k0_zero() {
    g_attn[threadIdx.x] = 0.0f;
}

// ---------------------------------------------------------------------------
// K1: qkv[oc(144), l] = W1[144x48] * x[48, l] + b1 via mma.sync tf32 (3-term
// split for fp32-grade accuracy). 9 warps = 9 oc m-tiles; W fragments live in
// registers for the whole kernel; X tile staged in smem pre-split hi/lo.
// ---------------------------------------------------------------------------
#define TPB1 4
__global__ __launch_bounds__(288) void k1_mma(const float* __restrict__ x,
                                              const float* __restrict__ w1,
                                              const float* __restrict__ b1) {
    extern __shared__ uint32_t sm[];
    uint32_t* Xhi = sm;
    uint32_t* Xlo = sm + 48 * XPITCH;

    const int tid  = threadIdx.x;
    const int warp = tid >> 5;          // 0..8 = oc m-tile
    const int lane = tid & 31;
    const int g    = lane >> 2;         // 0..7
    const int t4   = lane & 3;          // 0..3
    const int b    = blockIdx.y;
    const int oc0  = warp * 16;

    // W fragments (row-major A, m16k8): hi/lo split, resident in registers
    uint32_t ahi[6][4], alo[6][4];
#pragma unroll
    for (int ks = 0; ks < 6; ks++) {
        const int r0 = oc0 + g, r1 = oc0 + g + 8;
        const int c0 = ks * 8 + t4, c1 = c0 + 4;
        const float w00 = w1[r0 * 48 + c0];
        const float w10 = w1[r1 * 48 + c0];
        const float w01 = w1[r0 * 48 + c1];
        const float w11 = w1[r1 * 48 + c1];
        ahi[ks][0] = f2tf32(w00); alo[ks][0] = f2tf32(w00 - __uint_as_float(ahi[ks][0]));
        ahi[ks][1] = f2tf32(w10); alo[ks][1] = f2tf32(w10 - __uint_as_float(ahi[ks][1]));
        ahi[ks][2] = f2tf32(w01); alo[ks][2] = f2tf32(w01 - __uint_as_float(ahi[ks][2]));
        ahi[ks][3] = f2tf32(w11); alo[ks][3] = f2tf32(w11 - __uint_as_float(ahi[ks][3]));
    }
    const float bs0 = b1[oc0 + g];
    const float bs1 = b1[oc0 + g + 8];

#pragma unroll 1
    for (int t = 0; t < TPB1; t++) {
        const size_t l0 = ((size_t)blockIdx.x * TPB1 + t) * 128;
        __syncthreads();   // previous tile's reads done before restage
        for (int i = tid; i < 48 * 128; i += 288) {
            const int ic = i >> 7, j = i & 127;
            const float v = x[((size_t)b * C + ic) * LL + l0 + j];
            const uint32_t hi = f2tf32(v);
            Xhi[ic * XPITCH + j] = hi;
            Xlo[ic * XPITCH + j] = f2tf32(v - __uint_as_float(hi));
        }
        __syncthreads();

#pragma unroll 1
        for (int nt = 0; nt < 16; nt++) {
            const int ln = nt * 8;
            float c0 = bs0, c1 = bs0, c2 = bs1, c3 = bs1;
#pragma unroll
            for (int ks = 0; ks < 6; ks++) {
                const int kr = ks * 8 + t4;
                const uint32_t b0h = Xhi[kr * XPITCH + ln + g];
                const uint32_t b1h = Xhi[(kr + 4) * XPITCH + ln + g];
                const uint32_t b0l = Xlo[kr * XPITCH + ln + g];
                const uint32_t b1l = Xlo[(kr + 4) * XPITCH + ln + g];
                mma_tf32(c0, c1, c2, c3, ahi[ks][0], ahi[ks][1], ahi[ks][2], ahi[ks][3], b0h, b1h);
                mma_tf32(c0, c1, c2, c3, alo[ks][0], alo[ks][1], alo[ks][2], alo[ks][3], b0h, b1h);
                mma_tf32(c0, c1, c2, c3, ahi[ks][0], ahi[ks][1], ahi[ks][2], ahi[ks][3], b0l, b1l);
            }
            const size_t lc = l0 + ln + 2 * t4;
            *(float2*)&g_qkv[((size_t)b * C3 + oc0 + g) * LL + lc]     = make_float2(c0, c1);
            *(float2*)&g_qkv[((size_t)b * C3 + oc0 + g + 8) * LL + lc] = make_float2(c2, c3);
        }
    }
}

// ---------------------------------------------------------------------------
// K2: depthwise 3x3x3 over channel range (R10/R11 measured-best form)
// ---------------------------------------------------------------------------
template <int CHCNT>
__global__ __launch_bounds__(256, 3) void k2_dw(const float* __restrict__ wdw,
                                                const float* __restrict__ bdw,
                                                int ch_off) {
    const int gw   = blockIdx.x * 8 + (threadIdx.x >> 5);
    const int lane = threadIdx.x & 31;
    const int hp = gw & 31;
    const int t  = gw >> 5;
    const int ch = ch_off + t % CHCNT;
    const int b  = t / CHCNT;
    const int h0 = hp * 2;

    __shared__ float ws[28];
    if (threadIdx.x < 27) ws[threadIdx.x] = wdw[ch * 27 + threadIdx.x];
    if (threadIdx.x == 27) ws[27] = bdw[ch];
    __syncthreads();

    const float* base  = g_qkv + ((size_t)b * C3 + ch) * LL;
    float*       obase = g_dw  + ((size_t)b * C3 + ch) * LL;

    float2 rv[3][4];
    float  rl[3][4], rr[3][4];

    auto loadrow = [&](int d, int hh, int s) {
        const int hr = h0 + hh - 1;
        float2 v2;
        if (d < 0 || d >= DD || hr < 0 || hr >= HD) v2 = make_float2(0.f, 0.f);
        else v2 = ((const float2*)(base + (size_t)d * HW + hr * WD))[lane];
        float a = __shfl_up_sync(0xffffffffu, v2.y, 1);
        if (lane == 0) a = 0.f;
        float p = __shfl_down_sync(0xffffffffu, v2.x, 1);
        if (lane == 31) p = 0.f;
        rv[s][hh] = v2; rl[s][hh] = a; rr[s][hh] = p;
    };

#pragma unroll
    for (int hh = 0; hh < 4; hh++) {
        rv[0][hh] = make_float2(0.f, 0.f); rl[0][hh] = 0.f; rr[0][hh] = 0.f;
        loadrow(0, hh, 1);
        loadrow(1, hh, 2);
    }

#define K2_DD(SL, dd)                                                        \
    {                                                                        \
        _Pragma("unroll")                                                    \
        for (int hh = 0; hh < 3; hh++) {                                     \
            const int tb = ((dd) * 3 + hh) * 3;                              \
            const float w0 = ws[tb], w1 = ws[tb + 1], w2 = ws[tb + 2];       \
            {                                                                \
                const float2 v = rv[SL][hh];                                 \
                o0.x += w0 * rl[SL][hh] + w1 * v.x + w2 * v.y;               \
                o0.y += w0 * v.x        + w1 * v.y + w2 * rr[SL][hh];        \
            }                                                                \
            {                                                                \
                const float2 v = rv[SL][hh + 1];                             \
                o1.x += w0 * rl[SL][hh + 1] + w1 * v.x + w2 * v.y;           \
                o1.y += w0 * v.x            + w1 * v.y + w2 * rr[SL][hh + 1];\
            }                                                                \
        }                                                                    \
    }

#define K2_BODY(dcur, S0, S1, S2)                                            \
    {                                                                        \
        const float bias = ws[27];                                           \
        float2 o0 = make_float2(bias, bias);                                 \
        float2 o1 = make_float2(bias, bias);                                 \
        K2_DD(S0, 0)                                                         \
        K2_DD(S1, 1)                                                         \
        K2_DD(S2, 2)                                                         \
        ((float2*)(obase + (size_t)(dcur) * HW + h0 * WD))[lane]       = o0; \
        ((float2*)(obase + (size_t)(dcur) * HW + (h0 + 1) * WD))[lane] = o1; \
        _Pragma("unroll")                                                    \
        for (int hh = 0; hh < 4; hh++) loadrow((dcur) + 2, hh, S0);          \
    }

#pragma unroll 1
    for (int d = 0; d < 30; d += 3) {
        K2_BODY(d,     0, 1, 2)
        K2_BODY(d + 1, 1, 2, 0)
        K2_BODY(d + 2, 2, 0, 1)
    }
    K2_BODY(30, 0, 1, 2)
    K2_BODY(31, 1, 2, 0)
#undef K2_BODY
#undef K2_DD
}

// ---------------------------------------------------------------------------
// K3: attn += q.k^T over l (R9 measured-best, untouched)
// ---------------------------------------------------------------------------
__global__ __launch_bounds__(256) void k3_attn() {
    const int chunk = blockIdx.x;
    const int bh = blockIdx.y;
    const int z  = blockIdx.z;
    const int b = bh / HEADS, hd = bh % HEADS;

    const float* qb = g_dw + ((size_t)b * C3 + hd * CPH + 4 * z) * LL + (size_t)chunk * 2048;
    const float* kb = g_dw + ((size_t)b * C3 + C + hd * CPH) * LL + (size_t)chunk * 2048;

    float acc[32];
#pragma unroll
    for (int i = 0; i < 32; i++) acc[i] = 0.f;

    for (int it = 0; it < 8; it++) {
        const int l = it * 256 + threadIdx.x;
        float q[4], k[8];
#pragma unroll
        for (int i = 0; i < 4; i++) q[i] = qb[(size_t)i * LL + l];
#pragma unroll
        for (int i = 0; i < 8; i++) k[i] = kb[(size_t)i * LL + l];
#pragma unroll
        for (int i = 0; i < 4; i++)
#pragma unroll
            for (int j = 0; j < 8; j++)
                acc[i * 8 + j] += q[i] * k[j];
    }

    __shared__ float red[32];
    if (threadIdx.x < 32) red[threadIdx.x] = 0.f;
    __syncthreads();
    const int lane = threadIdx.x & 31;
#pragma unroll
    for (int v = 0; v < 32; v++) {
        float s = acc[v];
#pragma unroll
        for (int off = 16; off > 0; off >>= 1)
            s += __shfl_xor_sync(0xffffffffu, s, off);
        if (lane == 0) atomicAdd(&red[v], s);
    }
    __syncthreads();
    if (threadIdx.x < 32)
        atomicAdd(&g_attn[bh * 64 + 32 * z + threadIdx.x], red[threadIdx.x]);
}

// ---------------------------------------------------------------------------
// K4: softmax(scale*attn + mask), fold proj into per-batch 48x48 Weff
// ---------------------------------------------------------------------------
__global__ __launch_bounds__(256) void k4_soft(const float* __restrict__ mask,
                                               const float* __restrict__ wproj) {
    const int tid = threadIdx.x;
    __shared__ float A[BATCH * HEADS * CPH * CPH];
    const float scale = 0.40824829046386307f;  // 6^-0.5

    if (tid < BATCH * HEADS * CPH) {
        const int b = tid / (HEADS * CPH);
        const int r = tid % (HEADS * CPH);
        const int hd = r / CPH, c = r % CPH;
        float v[8];
        float mx = -1e30f;
#pragma unroll
        for (int j = 0; j < 8; j++) {
            v[j] = g_attn[((b * HEADS + hd) * CPH + c) * CPH + j] * scale
                 + mask[(b * CPH + c) * CPH + j];
            mx = fmaxf(mx, v[j]);
        }
        float s = 0.f;
#pragma unroll
        for (int j = 0; j < 8; j++) { v[j] = expf(v[j] - mx); s += v[j]; }
        const float inv = 1.f / s;
#pragma unroll
        for (int j = 0; j < 8; j++)
            A[((b * HEADS + hd) * CPH + c) * CPH + j] = v[j] * inv;
    }
    __syncthreads();

    for (int i = tid; i < BATCH * C * C; i += 256) {
        const int b = i / (C * C);
        const int r = i % (C * C);
        const int oc = r / C, c2 = r % C;
        const int hd = c2 / CPH, j = c2 % CPH;
        float s = 0.f;
#pragma unroll
        for (int ii = 0; ii < 8; ii++)
            s += wproj[oc * C + hd * CPH + ii]
               * A[((b * HEADS + hd) * CPH + ii) * CPH + j];
        g_weff[i] = s;
    }
}

// ---------------------------------------------------------------------------
// K5: out[48, l] = Weff[b] * v_dw + b_proj via mma.sync tf32 (3-term split).
// 6 warps: (m-tile 0..2) x (n-half 0..1). Same staging scheme as k1.
// ---------------------------------------------------------------------------
#define TPB5 8
__global__ __launch_bounds__(192) void k5_mma(const float* __restrict__ bproj,
                                              float* __restrict__ outp) {
    extern __shared__ uint32_t sm[];
    uint32_t* Vhi = sm;
    uint32_t* Vlo = sm + 48 * XPITCH;

    const int tid  = threadIdx.x;
    const int warp = tid >> 5;           // 0..5
    const int lane = tid & 31;
    const int g    = lane >> 2;
    const int t4   = lane & 3;
    const int b    = blockIdx.y;
    const int mw   = warp >> 1;          // 0..2 -> oc m-tile
    const int nh   = warp & 1;           // 0..1 -> l half
    const int oc0  = mw * 16;

    uint32_t ahi[6][4], alo[6][4];
    const float* wef = g_weff + b * C * C;
#pragma unroll
    for (int ks = 0; ks < 6; ks++) {
        const int r0 = oc0 + g, r1 = oc0 + g + 8;
        const int c0 = ks * 8 + t4, c1 = c0 + 4;
        const float w00 = wef[r0 * 48 + c0];
        const float w10 = wef[r1 * 48 + c0];
        const float w01 = wef[r0 * 48 + c1];
        const float w11 = wef[r1 * 48 + c1];
        ahi[ks][0] = f2tf32(w00); alo[ks][0] = f2tf32(w00 - __uint_as_float(ahi[ks][0]));
        ahi[ks][1] = f2tf32(w10); alo[ks][1] = f2tf32(w10 - __uint_as_float(ahi[ks][1]));
        ahi[ks][2] = f2tf32(w01); alo[ks][2] = f2tf32(w01 - __uint_as_float(ahi[ks][2]));
        ahi[ks][3] = f2tf32(w11); alo[ks][3] = f2tf32(w11 - __uint_as_float(ahi[ks][3]));
    }
    const float bs0 = bproj[oc0 + g];
    const float bs1 = bproj[oc0 + g + 8];

#pragma unroll 1
    for (int t = 0; t < TPB5; t++) {
        const size_t l0 = ((size_t)blockIdx.x * TPB5 + t) * 128;
        __syncthreads();
        for (int i = tid; i < 48 * 128; i += 192) {
            const int ic = i >> 7, j = i & 127;
            const float v = g_dw[((size_t)b * C3 + 2 * C + ic) * LL + l0 + j];
            const uint32_t hi = f2tf32(v);
            Vhi[ic * XPITCH + j] = hi;
            Vlo[ic * XPITCH + j] = f2tf32(v - __uint_as_float(hi));
        }
        __syncthreads();

#pragma unroll 1
        for (int nt = 0; nt < 8; nt++) {
            const int ln = nh * 64 + nt * 8;
            float c0 = bs0, c1 = bs0, c2 = bs1, c3 = bs1;
#pragma unroll
            for (int ks = 0; ks < 6; ks++) {
                const int kr = ks * 8 + t4;
                const uint32_t b0h = Vhi[kr * XPITCH + ln + g];
                const uint32_t b1h = Vhi[(kr + 4) * XPITCH + ln + g];
                const uint32_t b0l = Vlo[kr * XPITCH + ln + g];
                const uint32_t b1l = Vlo[(kr + 4) * XPITCH + ln + g];
                mma_tf32(c0, c1, c2, c3, ahi[ks][0], ahi[ks][1], ahi[ks][2], ahi[ks][3], b0h, b1h);
                mma_tf32(c0, c1, c2, c3, alo[ks][0], alo[ks][1], alo[ks][2], alo[ks][3], b0h, b1h);
                mma_tf32(c0, c1, c2, c3, ahi[ks][0], ahi[ks][1], ahi[ks][2], ahi[ks][3], b0l, b1l);
            }
            const size_t lc = l0 + ln + 2 * t4;
            *(float2*)&outp[((size_t)b * C + oc0 + g) * LL + lc]     = make_float2(c0, c1);
            *(float2*)&outp[((size_t)b * C + oc0 + g + 8) * LL + lc] = make_float2(c2, c3);
        }
    }
}

// ---------------------------------------------------------------------------
// Launch: fork k2v onto side stream (R11 pattern, capture-legal fork-join).
// ---------------------------------------------------------------------------
extern "C" void kernel_launch(void* const* d_in, const int* in_sizes, int n_in,
                              void* d_out, int out_size) {
    const float* x      = (const float*)d_in[0];
    const float* mask   = (const float*)d_in[1];
    const float* w_qkv1 = (const float*)d_in[2];
    const float* b_qkv1 = (const float*)d_in[3];
    const float* w_dw   = (const float*)d_in[4];
    const float* b_dw   = (const float*)d_in[5];
    const float* w_proj = (const float*)d_in[6];
    const float* b_proj = (const float*)d_in[7];
    float* out = (float*)d_out;

    cudaFuncSetAttribute(k1_mma, cudaFuncAttributeMaxDynamicSharedMemorySize, SM_TC);
    cudaFuncSetAttribute(k5_mma, cudaFuncAttributeMaxDynamicSharedMemorySize, SM_TC);

    cudaStream_t s1;
    cudaEvent_t eA, eB;
    cudaStreamCreate(&s1);
    cudaEventCreateWithFlags(&eA, cudaEventDisableTiming);
    cudaEventCreateWithFlags(&eB, cudaEventDisableTiming);

    k0_zero<<<1, BATCH * HEADS * CPH * CPH>>>();
    k1_mma<<<dim3(LL / 128 / TPB1, BATCH), 288, SM_TC>>>(x, w_qkv1, b_qkv1);

    cudaEventRecord(eA, 0);
    cudaStreamWaitEvent(s1, eA, 0);

    // side stream: v-channel depthwise
    k2_dw<C><<<(BATCH * C * (HD / 2)) / 8, 256, 0, s1>>>(w_dw, b_dw, 2 * C);
    cudaEventRecord(eB, s1);

    // main stream: qk depthwise -> attention -> softmax/proj-fold
    k2_dw<2 * C><<<(BATCH * 2 * C * (HD / 2)) / 8, 256>>>(w_dw, b_dw, 0);
    k3_attn<<<dim3(LL / 2048, BATCH * HEADS, 2), 256>>>();
    k4_soft<<<1, 256>>>(mask, w_proj);

    cudaStreamWaitEvent(0, eB, 0);
    k5_mma<<<dim3(LL / 128 / TPB5, BATCH), 192, SM_TC>>>(b_proj, out);
}